// round 3
// baseline (speedup 1.0000x reference)
#include <cuda_runtime.h>

// Thin-plate spline (order 3), 1024x1024 grid, batch 4 (all batches identical).
//   out[b,y,x] = sum_m ((x-tx_m)^2 + (y-ty_m)^2)^{3/2} * ww_m/2^40 + v0*x + v1*y + v2
//
// Two-kernel scheme:
//   A) compute coarse RBF field on a 257x257 grid (stride 4 in x and y) ONCE
//      into a __device__ buffer (~264 KB, L2-resident). Curvature of the RBF
//      field is ~1.4e-7 abs, so bilinear interp error ~6e-7 abs (~1e-8 rel,
//      budget 1e-3; measured 6.3e-8 with this stride in R2).
//   B) per-pixel bilinear interp of the coarse field + exact linear term,
//      4x float4 stores (one per batch). Pure streaming, no barriers.

#define WDIM 1024
#define HDIM 1024
#define MPTS 16
#define CC 257                 // coarse samples per dim: x,y = 0,4,...,1024
#define CN (CC * CC)

__device__ float g_coarse[CN];

__device__ __forceinline__ float sqrt_approx(float v) {
    float r;
    asm("sqrt.approx.f32 %0, %1;" : "=f"(r) : "f"(v));
    return r;
}

// ---- kernel A: coarse RBF grid -------------------------------------------
__global__ void __launch_bounds__(256) coarse_kernel(
    const float* __restrict__ train_points,  // [16,2] in [0,1]
    const float* __restrict__ ww)            // [16]
{
    const int idx = blockIdx.x * blockDim.x + threadIdx.x;
    if (idx >= CN) return;
    const int cy = idx / CC;
    const int cx = idx - cy * CC;
    const float fx = (float)(cx << 2);
    const float fy = (float)(cy << 2);

    float acc = 0.0f;
#pragma unroll
    for (int m = 0; m < MPTS; ++m) {
        const float tx = __ldg(&train_points[2 * m])     * 1024.0f;
        const float ty = __ldg(&train_points[2 * m + 1]) * 1024.0f;
        const float w  = __ldg(&ww[m]) * (1.0f / 1099511627776.0f); // * 2^-40
        const float dx = fx - tx;
        const float dy = fy - ty;
        const float r2 = fmaf(dx, dx, dy * dy);
        acc = fmaf(r2 * w, sqrt_approx(r2), acc);   // + w * r2^{3/2}
    }
    g_coarse[idx] = acc;
}

// ---- kernel B: interpolate + linear term + store -------------------------
__global__ void __launch_bounds__(256) interp_kernel(
    const float* __restrict__ vw,   // [3]
    float* __restrict__ out,        // [B, 1024, 1024]
    int B)
{
    const int y    = blockIdx.x;        // 0..1023
    const int lane = threadIdx.x;       // coarse cell index = x0/4
    const int x0   = lane << 2;

    const int   cy  = y >> 2;
    const float fyf = 0.25f * (float)(y & 3);

    const float* rT = g_coarse + cy * CC;
    const float* rB = rT + CC;
    const float gT0 = __ldg(rT + lane);
    const float gT1 = __ldg(rT + lane + 1);
    const float gB0 = __ldg(rB + lane);
    const float gB1 = __ldg(rB + lane + 1);

    const float gL = fmaf(gB0 - gT0, fyf, gT0);   // rbf at (x0,   y)
    const float gR = fmaf(gB1 - gT1, fyf, gT1);   // rbf at (x0+4, y)
    const float dg = (gR - gL) * 0.25f;           // rbf slope per pixel in x

    const float v0 = __ldg(&vw[0]);
    const float v1 = __ldg(&vw[1]);
    const float v2 = __ldg(&vw[2]);

    const float base  = gL + fmaf((float)y, v1, v2) + (float)x0 * v0;
    const float slope = dg + v0;

    float4 v;
    v.x = base;
    v.y = base + slope;
    v.z = fmaf(slope, 2.0f, base);
    v.w = fmaf(slope, 3.0f, base);

    const size_t off   = (size_t)y * WDIM + x0;
    const size_t plane = (size_t)WDIM * HDIM;
#pragma unroll 4
    for (int b = 0; b < B; ++b) {
        *reinterpret_cast<float4*>(out + b * plane + off) = v;
    }
}

extern "C" void kernel_launch(void* const* d_in, const int* in_sizes, int n_in,
                              void* d_out, int out_size)
{
    // inputs: x [B,1024,1024,1] (shape only), train_points [1,16,2],
    //         ww [1,16,1], vw [1,3,1]
    const float* train_points = (const float*)d_in[1];
    const float* ww           = (const float*)d_in[2];
    const float* vw           = (const float*)d_in[3];
    float* out = (float*)d_out;

    const int B = in_sizes[0] / (WDIM * HDIM);  // = 4

    coarse_kernel<<<(CN + 255) / 256, 256>>>(train_points, ww);
    interp_kernel<<<HDIM, 256>>>(vw, out, B);
}

// round 4
// speedup vs baseline: 1.1667x; 1.1667x over previous
#include <cuda_runtime.h>

// Thin-plate spline (order 3), 1024x1024 grid, batch 4 (all batches identical).
//   out[b,y,x] = sum_m ((x-tx_m)^2 + (y-ty_m)^2)^{3/2} * ww_m/2^40 + v0*x + v1*y + v2
//
// Fused single kernel, one wave (256 blocks x 1024 thr, 2 blocks/SM).
// Each block owns a 16-row x 256-col tile. Phase 1 computes the RBF field on
// a stride-4 coarse grid for the tile (5 x 65 = 325 samples, 1.27x redundancy)
// with a fully-unrolled m-loop (16 independent sqrt chains). Phase 2 bilinearly
// interpolates (RBF curvature ~1.4e-7 abs => interp err ~6e-7 abs, ~1e-8 rel;
// measured 6.3e-8) plus exact linear term; float4 stores x 4 batches.

#define WDIM 1024
#define HDIM 1024
#define MPTS 16
#define TROWS 16          // tile rows
#define TCOLS 256         // tile cols
#define CROWS 5           // coarse rows per tile  (TROWS/4 + 1)
#define CCOLS 65          // coarse cols per tile  (TCOLS/4 + 1)

__device__ __forceinline__ float sqrt_approx(float v) {
    float r;
    asm("sqrt.approx.f32 %0, %1;" : "=f"(r) : "f"(v));
    return r;
}

__global__ void __launch_bounds__(1024, 2) spline_kernel(
    const float* __restrict__ train_points,  // [16,2] in [0,1]
    const float* __restrict__ ww,            // [16]
    const float* __restrict__ vw,            // [3]
    float* __restrict__ out,                 // [B, 1024, 1024]
    int B)
{
    __shared__ float g[CROWS][CCOLS];        // coarse RBF samples for this tile

    const int t  = threadIdx.x;
    const int x0_tile = blockIdx.x << 8;     // tile origin x (0,256,512,768)
    const int y0_tile = blockIdx.y << 4;     // tile origin y (0..1008 step 16)

    // ---- phase 1: coarse RBF samples (stride 4 both dims) ----
    if (t < CROWS * CCOLS) {
        const int row = t / CCOLS;           // 0..4
        const int col = t - row * CCOLS;     // 0..64
        const float fx = (float)(x0_tile + (col << 2));
        const float fy = (float)(y0_tile + (row << 2));
        float acc = 0.0f;
#pragma unroll
        for (int m = 0; m < MPTS; ++m) {
            const float tx = __ldg(&train_points[2 * m])     * 1024.0f;
            const float ty = __ldg(&train_points[2 * m + 1]) * 1024.0f;
            const float w  = __ldg(&ww[m]) * (1.0f / 1099511627776.0f); // *2^-40
            const float dx = fx - tx;
            const float dy = fy - ty;
            const float r2 = fmaf(dx, dx, dy * dy);
            acc = fmaf(r2 * w, sqrt_approx(r2), acc);   // + w * r2^{3/2}
        }
        g[row][col] = acc;
    }
    __syncthreads();

    // ---- phase 2: bilinear interp + exact linear term + stores ----
    const int r = t >> 6;                    // 0..15: row within tile
    const int c = t & 63;                    // 0..63: coarse cell within tile
    const int y  = y0_tile + r;
    const int x0 = x0_tile + (c << 2);

    const int   cr  = r >> 2;
    const float fyf = 0.25f * (float)(r & 3);

    const float gT0 = g[cr][c];
    const float gT1 = g[cr][c + 1];
    const float gB0 = g[cr + 1][c];
    const float gB1 = g[cr + 1][c + 1];

    const float gL = fmaf(gB0 - gT0, fyf, gT0);   // rbf at (x0,   y)
    const float gR = fmaf(gB1 - gT1, fyf, gT1);   // rbf at (x0+4, y)
    const float dg = (gR - gL) * 0.25f;           // rbf slope per pixel in x

    const float v0 = __ldg(&vw[0]);
    const float v1 = __ldg(&vw[1]);
    const float v2 = __ldg(&vw[2]);

    const float base  = gL + fmaf((float)y, v1, v2) + (float)x0 * v0;
    const float slope = dg + v0;

    float4 v;
    v.x = base;
    v.y = base + slope;
    v.z = fmaf(slope, 2.0f, base);
    v.w = fmaf(slope, 3.0f, base);

    const size_t off   = (size_t)y * WDIM + x0;
    const size_t plane = (size_t)WDIM * HDIM;
#pragma unroll 4
    for (int b = 0; b < B; ++b) {
        *reinterpret_cast<float4*>(out + b * plane + off) = v;
    }
}

extern "C" void kernel_launch(void* const* d_in, const int* in_sizes, int n_in,
                              void* d_out, int out_size)
{
    // inputs: x [B,1024,1024,1] (shape only), train_points [1,16,2],
    //         ww [1,16,1], vw [1,3,1]
    const float* train_points = (const float*)d_in[1];
    const float* ww           = (const float*)d_in[2];
    const float* vw           = (const float*)d_in[3];
    float* out = (float*)d_out;

    const int B = in_sizes[0] / (WDIM * HDIM);  // = 4

    dim3 grid(WDIM / TCOLS, HDIM / TROWS);   // 4 x 64 = 256 blocks, one wave
    dim3 block(1024);
    spline_kernel<<<grid, block>>>(train_points, ww, vw, out, B);
}

// round 5
// speedup vs baseline: 1.2353x; 1.0588x over previous
#include <cuda_runtime.h>
#include <cstdint>

// Thin-plate spline (order 3), 1024x1024 grid, batch 4 (all batches identical).
//   out[b,y,x] = sum_m ((x-tx_m)^2 + (y-ty_m)^2)^{3/2} * ww_m/2^40 + v0*x + v1*y + v2
//
// Strategy (R5): per-thread scattered STG.128s were the wall (R3 interp-only
// kernel already cost 6.3us with no math). Each block now computes a 4-row
// full-width stripe into SMEM and issues 4x cp.async.bulk (16KB contiguous
// per batch plane) so the TMA/LTS path drains the stores instead of the
// LSU/L1 path. RBF field evaluated on a stride-4 coarse grid + bilinear
// interp (abs err ~6e-7 vs values O(100..1000); measured rel_err 6.3e-8).

#define WDIM 1024
#define HDIM 1024
#define MPTS 16
#define CC   257                      // coarse cols: x = 0,4,...,1024
#define RPB  4                        // rows per block
#define TILE_BYTES (RPB * WDIM * 4)   // 16 KB per batch plane

__device__ __forceinline__ float sqrt_approx(float v) {
    float r;
    asm("sqrt.approx.f32 %0, %1;" : "=f"(r) : "f"(v));
    return r;
}

__device__ __forceinline__ uint32_t smem_u32(const void* p) {
    uint32_t a;
    asm("{ .reg .u64 t; cvta.to.shared.u64 t, %1; cvt.u32.u64 %0, t; }"
        : "=r"(a) : "l"(p));
    return a;
}

__global__ void __launch_bounds__(1024, 2) spline_kernel(
    const float* __restrict__ train_points,  // [16,2] in [0,1]
    const float* __restrict__ ww,            // [16]
    const float* __restrict__ vw,            // [3]
    float* __restrict__ out,                 // [B, 1024, 1024]
    int B)
{
    __shared__ float4 tile[RPB * WDIM / 4];  // 16 KB: 4 rows x 1024 px
    __shared__ float  g[2][CC];              // coarse RBF rows at y0, y0+4

    const int t  = threadIdx.x;
    const int y0 = blockIdx.x << 2;          // stripe rows y0..y0+3

    // ---- phase 1: coarse RBF samples (x stride 4; rows y0 and y0+4) ----
    if (t < 2 * CC) {
        const int row = (t >= CC) ? 1 : 0;
        const int col = t - row * CC;
        const float fx = (float)(col << 2);
        const float fy = (float)(y0 + (row << 2));
        float acc = 0.0f;
#pragma unroll
        for (int m = 0; m < MPTS; ++m) {
            const float tx = __ldg(&train_points[2 * m])     * 1024.0f;
            const float ty = __ldg(&train_points[2 * m + 1]) * 1024.0f;
            const float w  = __ldg(&ww[m]) * (1.0f / 1099511627776.0f); // *2^-40
            const float dx = fx - tx;
            const float dy = fy - ty;
            const float r2 = fmaf(dx, dx, dy * dy);
            acc = fmaf(r2 * w, sqrt_approx(r2), acc);   // + w * r2^{3/2}
        }
        g[row][col] = acc;
    }
    __syncthreads();

    // ---- phase 2: bilinear interp + exact linear term -> smem tile ----
    {
        const int r    = t >> 8;         // 0..3: row within stripe
        const int lane = t & 255;        // coarse cell = x0/4
        const int y    = y0 + r;
        const int x0   = lane << 2;
        const float fyf = 0.25f * (float)r;

        const float gT0 = g[0][lane];
        const float gT1 = g[0][lane + 1];
        const float gB0 = g[1][lane];
        const float gB1 = g[1][lane + 1];

        const float gL = fmaf(gB0 - gT0, fyf, gT0);   // rbf at (x0,   y)
        const float gR = fmaf(gB1 - gT1, fyf, gT1);   // rbf at (x0+4, y)
        const float dg = (gR - gL) * 0.25f;           // rbf x-slope per pixel

        const float v0 = __ldg(&vw[0]);
        const float v1 = __ldg(&vw[1]);
        const float v2 = __ldg(&vw[2]);

        const float base  = gL + fmaf((float)y, v1, v2) + (float)x0 * v0;
        const float slope = dg + v0;

        float4 v;
        v.x = base;
        v.y = base + slope;
        v.z = fmaf(slope, 2.0f, base);
        v.w = fmaf(slope, 3.0f, base);

        tile[t] = v;   // row-major: (r*1024 + x0)/4 == t  -> conflict-free STS.128
    }
    __syncthreads();

    // ---- phase 3: bulk-async stores, one 16KB copy per batch plane ----
    if (t == 0) {
        asm volatile("fence.proxy.async.shared::cta;" ::: "memory");
        const uint32_t src = smem_u32(tile);
        const size_t plane = (size_t)WDIM * HDIM;
        float* dst0 = out + (size_t)y0 * WDIM;
#pragma unroll 4
        for (int b = 0; b < B; ++b) {
            asm volatile(
                "cp.async.bulk.global.shared::cta.bulk_group [%0], [%1], %2;"
                :: "l"(dst0 + b * plane), "r"(src), "n"(TILE_BYTES)
                : "memory");
        }
        asm volatile("cp.async.bulk.commit_group;" ::: "memory");
        asm volatile("cp.async.bulk.wait_group 0;" ::: "memory");
    }
}

extern "C" void kernel_launch(void* const* d_in, const int* in_sizes, int n_in,
                              void* d_out, int out_size)
{
    // inputs: x [B,1024,1024,1] (shape only), train_points [1,16,2],
    //         ww [1,16,1], vw [1,3,1]
    const float* train_points = (const float*)d_in[1];
    const float* ww           = (const float*)d_in[2];
    const float* vw           = (const float*)d_in[3];
    float* out = (float*)d_out;

    const int B = in_sizes[0] / (WDIM * HDIM);  // = 4

    dim3 grid(HDIM / RPB);    // 256 blocks, one per 4-row stripe -> one wave
    dim3 block(1024);
    spline_kernel<<<grid, block>>>(train_points, ww, vw, out, B);
}